// round 15
// baseline (speedup 1.0000x reference)
#include <cuda_runtime.h>
#include <cuda_bf16.h>
#include <math.h>
#include <cstdint>

// NeRFRenderer null-scattering marcher (max_depths=1): all tot replicas of a
// ray are identical -> single per-ray eval: ray-sphere hit, equirect env-map
// bilinear sample, attenuate.
//
// inputs: d_in[0] rays_o f32[N,3], d_in[1] rays_d f32[N,3],
//         d_in[2] env_map f32[1,3,16,32], d_in[3..4] step counts (cancel).
// output: f32 [N,3]
//
// R14: champion geometry (256 CTAs x 64 threads, register-staged float4 env
// preload overlapping the ray math, single __syncthreads) + algebraic t
// (|d|=1 -> no divide) + simplified bilinear bounds: from the coordinate
// ranges (ix in [-0.5,31.5], iy in [-0.5,15.5]) only the low-side check can
// fail for corner 0 and the high-side for corner 1, so zero-padding becomes
// 4 one-sided weight selects instead of 4 two-sided predicates + 8 clamps.

#define ENV_H 16
#define ENV_W 32
#define ENV_HW (ENV_H * ENV_W)
#define ENV_ELEMS (3 * ENV_HW)              // 1536 floats = 384 float4
#define SIGMA_MAJORANT 0.1f
#define PI_F 3.14159265358979323846f
#define THREADS 64
#define F4_PER_THREAD (ENV_ELEMS / 4 / THREADS)   // 6

// fast acos, max err ~6.7e-5 rad
__device__ __forceinline__ float acos_fast(float x) {
    float ax = fabsf(x);
    float r = sqrtf(1.0f - ax) *
              (1.5707288f + ax * (-0.2121144f + ax * (0.0742610f + ax * (-0.0187293f))));
    return x < 0.0f ? (PI_F - r) : r;
}

// atan on [0,1], max err ~1e-5 rad
__device__ __forceinline__ float atan_poly(float a) {
    float s = a * a;
    return a * (0.9998660f + s * (-0.3302995f + s * (0.1801410f +
               s * (-0.0851330f + s * 0.0208351f))));
}

// fast atan2 (returns 0 at (0,0), matching nan_to_num in the reference)
__device__ __forceinline__ float atan2_fast(float y, float x) {
    float ay = fabsf(y), ax = fabsf(x);
    bool swap = ay > ax;
    float num = swap ? ax : ay;
    float den = swap ? ay : ax;
    den = fmaxf(den, 1e-30f);
    float r = atan_poly(__fdividef(num, den));
    if (swap) r = 1.57079632679f - r;
    if (x < 0.0f) r = PI_F - r;
    return y < 0.0f ? -r : r;
}

__global__ void __launch_bounds__(THREADS)
nerf_env_kernel(const float* __restrict__ rays_o,
                const float* __restrict__ rays_d,
                const float* __restrict__ env,
                float* __restrict__ out,
                int N)
{
    __shared__ float s_env[ENV_ELEMS];

    const int i = blockIdx.x * THREADS + threadIdx.x;
    const bool active = (i < N);
    const int ii = active ? i : 0;
    const int t = threadIdx.x;

    // issue ray loads first
    const float ox = rays_o[3 * ii + 0];
    const float oy = rays_o[3 * ii + 1];
    const float oz = rays_o[3 * ii + 2];
    const float dx = rays_d[3 * ii + 0];
    const float dy = rays_d[3 * ii + 1];
    const float dz = rays_d[3 * ii + 2];

    // issue env preload: 384 float4 total, 6 per thread
    const float4* __restrict__ env4 = (const float4*)env;
    float4 e[F4_PER_THREAD];
#pragma unroll
    for (int k = 0; k < F4_PER_THREAD; k++)
        e[k] = env4[t + k * THREADS];

    // ---- env-independent math (overlaps the load latency above) ----
    // |d| = 1  =>  t = -m + sqrt(m^2 - c),  m = o.d,  c = o.o - 1
    const float m = ox * dx + oy * dy + oz * dz;
    const float c = ox * ox + oy * oy + oz * oz - 1.0f;
    const float disc = m * m - c;            // = delta/4
    const float sq = sqrtf(disc > 0.0f ? disc : 0.25f);
    const float t_hit = sq - m;
    const bool valid = (disc > 0.0f) && (t_hit >= 0.0f);

    const float hx = ox + dx * t_hit;
    const float hy = oy + dy * t_hit;
    const float hz = oz + dz * t_hit;

    // grid-sample coords, affine folded in:
    //   iy = (H/2)*(atan2/pi) + (H-1)/2 ;  ix = (W/pi)*acos(yc) - 0.5
    const float iy = atan2_fast(hx, -hz) * ((float)ENV_H * 0.5f / PI_F)
                   + ((float)ENV_H - 1.0f) * 0.5f;
    const float yc = fminf(fmaxf(hy, -1.0f + 1e-6f), 1.0f - 1e-6f);
    const float ix = acos_fast(yc) * ((float)ENV_W / PI_F) - 0.5f;

    const float fx0 = floorf(ix);
    const float fy0 = floorf(iy);
    const float wx1 = ix - fx0;
    const float wy1 = iy - fy0;
    const int x0 = (int)fx0;                 // in [-1, 31]
    const int y0 = (int)fy0;                 // in [-1, 15]

    // one-sided zero-padding: corner0 can only fail low, corner1 only high
    const float wxa = (x0 >= 0)         ? (1.0f - wx1) : 0.0f;
    const float wxb = (x0 <= ENV_W - 2) ? wx1          : 0.0f;
    const float wya = (y0 >= 0)         ? (1.0f - wy1) : 0.0f;
    const float wyb = (y0 <= ENV_H - 2) ? wy1          : 0.0f;
    const int xi0 = max(x0, 0);
    const int xi1 = min(x0 + 1, ENV_W - 1);
    const int yi0 = max(y0, 0);
    const int yi1 = min(y0 + 1, ENV_H - 1);
    const int b00 = yi0 * ENV_W + xi0;
    const int b01 = yi0 * ENV_W + xi1;
    const int b10 = yi1 * ENV_W + xi0;
    const int b11 = yi1 * ENV_W + xi1;

    // ---- commit env to smem, sync, gather ----
    float4* s_env4 = (float4*)s_env;
#pragma unroll
    for (int k = 0; k < F4_PER_THREAD; k++)
        s_env4[t + k * THREADS] = e[k];
    __syncthreads();

    float acc[3];
#pragma unroll
    for (int ch = 0; ch < 3; ch++) {
        const float* s = s_env + ch * ENV_HW;
        const float row0 = wxa * s[b00] + wxb * s[b01];
        const float row1 = wxa * s[b10] + wxb * s[b11];
        acc[ch] = wya * row0 + wyb * row1;
    }

    if (active) {
        const float st = SIGMA_MAJORANT * t_hit;
        out[3 * i + 0] = valid ? __expf(acc[0] - st) : 0.0f;
        out[3 * i + 1] = valid ? __expf(acc[1] - st) : 0.0f;
        out[3 * i + 2] = valid ? __expf(acc[2] - st) : 0.0f;
    }
}

extern "C" void kernel_launch(void* const* d_in, const int* in_sizes, int n_in,
                              void* d_out, int out_size)
{
    const float* rays_o = (const float*)d_in[0];
    const float* rays_d = (const float*)d_in[1];
    const float* env    = (const float*)d_in[2];
    float* out = (float*)d_out;

    const int N = in_sizes[0] / 3;
    const int blocks = (N + THREADS - 1) / THREADS;
    nerf_env_kernel<<<blocks, THREADS>>>(rays_o, rays_d, env, out, N);
}